// round 14
// baseline (speedup 1.0000x reference)
#include <cuda_runtime.h>

#define POOL 7
#define FM_W 64
#define C2   64   // float2 chunks per pixel (128 fp32 channels)

__global__ __launch_bounds__(224, 7)
void roi_pool_kernel(const float2* __restrict__ fm2,
                     const int* __restrict__ rois,
                     float2* __restrict__ out2,
                     int n_rois)
{
    const int roi = blockIdx.x;
    if (roi >= n_rois) return;

    const int t    = threadIdx.x;
    const int warp = t >> 5;     // 0..6  == output row py
    const int lane = t & 31;

    // ROI descriptor (4-int broadcast load; L1-resident after first touch)
    const int rx1 = __ldg(rois + roi * 4 + 0);
    const int ry1 = __ldg(rois + roi * 4 + 1);
    const int rx2 = __ldg(rois + roi * 4 + 2);
    const int ry2 = __ldg(rois + roi * 4 + 3);

    const float live = ((rx1 | ry1 | rx2 | ry2) == 0) ? 0.0f : 1.0f;

    // ---- y axis: computed once (py = warp), exactly matching the reference:
    //      yc = clip(((j+0.5)*hf)/7 - 0.5, 0, hf-1); y0 = floor(yc)
    const int   hh = max(ry2 - ry1, 1);
    const float hf = (float)hh;
    float yc = __fdiv_rn(((float)warp + 0.5f) * hf, (float)POOL) - 0.5f;
    yc = fminf(fmaxf(yc, 0.0f), hf - 1.0f);
    const int   y0  = (int)floorf(yc);
    const float wy  = yc - (float)y0;
    const int   rb0 = (y0 + ry1) * FM_W;                 // row base, top
    const int   rb1 = (min(y0 + 1, hh - 1) + ry1) * FM_W; // row base, bottom
    const float wyn = (1.0f - wy) * live;                // folded zero-ROI mask
    const float wyp = wy * live;

    const int   ww = max(rx2 - rx1, 1);
    const float wf = (float)ww;

    float2* obase = out2 + (size_t)roi * (POOL * POOL * C2)
                         + warp * (POOL * C2) + lane;

#pragma unroll
    for (int px = 0; px < POOL; px++) {
        // ---- x axis: recomputed by all lanes (trades ALU slots for L1 port) ----
        float xc = __fdiv_rn(((float)px + 0.5f) * wf, (float)POOL) - 0.5f;
        xc = fminf(fmaxf(xc, 0.0f), wf - 1.0f);
        const int   x0  = (int)floorf(xc);
        const float wx  = xc - (float)x0;
        const int   xa0 = x0 + rx1;
        const int   xa1 = min(x0 + 1, ww - 1) + rx1;

        const int o00 = (rb0 + xa0) * C2;
        const int o01 = (rb0 + xa1) * C2;
        const int o10 = (rb1 + xa0) * C2;
        const int o11 = (rb1 + xa1) * C2;

        const float w00 = wyn * (1.0f - wx);
        const float w01 = wyn * wx;
        const float w10 = wyp * (1.0f - wx);
        const float w11 = wyp * wx;

        // sweep A: bytes [0,256) of each pixel; sweep B: bytes [256,512)
        const float2 a00 = __ldg(fm2 + o00 + lane);
        const float2 a01 = __ldg(fm2 + o01 + lane);
        const float2 a10 = __ldg(fm2 + o10 + lane);
        const float2 a11 = __ldg(fm2 + o11 + lane);
        const float2 b00 = __ldg(fm2 + o00 + 32 + lane);
        const float2 b01 = __ldg(fm2 + o01 + 32 + lane);
        const float2 b10 = __ldg(fm2 + o10 + 32 + lane);
        const float2 b11 = __ldg(fm2 + o11 + 32 + lane);

        float2 ra, rb;
        ra.x = fmaf(a00.x, w00, fmaf(a01.x, w01, fmaf(a10.x, w10, a11.x * w11)));
        ra.y = fmaf(a00.y, w00, fmaf(a01.y, w01, fmaf(a10.y, w10, a11.y * w11)));
        rb.x = fmaf(b00.x, w00, fmaf(b01.x, w01, fmaf(b10.x, w10, b11.x * w11)));
        rb.y = fmaf(b00.y, w00, fmaf(b01.y, w01, fmaf(b10.y, w10, b11.y * w11)));

        obase[px * C2]      = ra;
        obase[px * C2 + 32] = rb;
    }
}

extern "C" void kernel_launch(void* const* d_in, const int* in_sizes, int n_in,
                              void* d_out, int out_size)
{
    const float2* fm2  = (const float2*)d_in[0];   // (1,64,64,128) fp32
    const int*    rois = (const int*)d_in[1];      // (1,N,4) int32
    float2*       out2 = (float2*)d_out;           // (1,N,7,7,128) fp32

    const int n_rois = in_sizes[1] / 4;

    roi_pool_kernel<<<n_rois, 224>>>(fm2, rois, out2, n_rois);
}

// round 15
// speedup vs baseline: 1.0050x; 1.0050x over previous
#include <cuda_runtime.h>

#define POOL 7
#define FM_W 64
#define C2   64   // float2 chunks per pixel (128 fp32 channels)

__global__ __launch_bounds__(224, 7)
void roi_pool_kernel(const float2* __restrict__ fm2,
                     const int* __restrict__ rois,
                     float2* __restrict__ out2,
                     int n_rois)
{
    const int roi = blockIdx.x;
    if (roi >= n_rois) return;

    const int t    = threadIdx.x;
    const int warp = t >> 5;     // 0..6  == output row py
    const int lane = t & 31;

    // ROI descriptor (4-int broadcast load; L1-resident after first touch)
    const int rx1 = __ldg(rois + roi * 4 + 0);
    const int ry1 = __ldg(rois + roi * 4 + 1);
    const int rx2 = __ldg(rois + roi * 4 + 2);
    const int ry2 = __ldg(rois + roi * 4 + 3);

    const float live = ((rx1 | ry1 | rx2 | ry2) == 0) ? 0.0f : 1.0f;

    // ---- y axis: computed once (py = warp), exactly matching the reference:
    //      yc = clip(((j+0.5)*hf)/7 - 0.5, 0, hf-1); y0 = floor(yc)
    const int   hh = max(ry2 - ry1, 1);
    const float hf = (float)hh;
    float yc = __fdiv_rn(((float)warp + 0.5f) * hf, (float)POOL) - 0.5f;
    yc = fminf(fmaxf(yc, 0.0f), hf - 1.0f);
    const int   y0  = (int)floorf(yc);
    const float wy  = yc - (float)y0;
    const int   rb0 = (y0 + ry1) * FM_W;                 // row base, top
    const int   rb1 = (min(y0 + 1, hh - 1) + ry1) * FM_W; // row base, bottom
    const float wyn = (1.0f - wy) * live;                // folded zero-ROI mask
    const float wyp = wy * live;

    const int   ww = max(rx2 - rx1, 1);
    const float wf = (float)ww;

    float2* obase = out2 + (size_t)roi * (POOL * POOL * C2)
                         + warp * (POOL * C2) + lane;

#pragma unroll
    for (int px = 0; px < POOL; px++) {
        // ---- x axis: recomputed by all lanes (trades ALU slots for L1 port) ----
        float xc = __fdiv_rn(((float)px + 0.5f) * wf, (float)POOL) - 0.5f;
        xc = fminf(fmaxf(xc, 0.0f), wf - 1.0f);
        const int   x0  = (int)floorf(xc);
        const float wx  = xc - (float)x0;
        const int   xa0 = x0 + rx1;
        const int   xa1 = min(x0 + 1, ww - 1) + rx1;

        const int o00 = (rb0 + xa0) * C2;
        const int o01 = (rb0 + xa1) * C2;
        const int o10 = (rb1 + xa0) * C2;
        const int o11 = (rb1 + xa1) * C2;

        const float w00 = wyn * (1.0f - wx);
        const float w01 = wyn * wx;
        const float w10 = wyp * (1.0f - wx);
        const float w11 = wyp * wx;

        // sweep A: bytes [0,256) of each pixel; sweep B: bytes [256,512)
        const float2 a00 = __ldg(fm2 + o00 + lane);
        const float2 a01 = __ldg(fm2 + o01 + lane);
        const float2 a10 = __ldg(fm2 + o10 + lane);
        const float2 a11 = __ldg(fm2 + o11 + lane);
        const float2 b00 = __ldg(fm2 + o00 + 32 + lane);
        const float2 b01 = __ldg(fm2 + o01 + 32 + lane);
        const float2 b10 = __ldg(fm2 + o10 + 32 + lane);
        const float2 b11 = __ldg(fm2 + o11 + 32 + lane);

        float2 ra, rb;
        ra.x = fmaf(a00.x, w00, fmaf(a01.x, w01, fmaf(a10.x, w10, a11.x * w11)));
        ra.y = fmaf(a00.y, w00, fmaf(a01.y, w01, fmaf(a10.y, w10, a11.y * w11)));
        rb.x = fmaf(b00.x, w00, fmaf(b01.x, w01, fmaf(b10.x, w10, b11.x * w11)));
        rb.y = fmaf(b00.y, w00, fmaf(b01.y, w01, fmaf(b10.y, w10, b11.y * w11)));

        obase[px * C2]      = ra;
        obase[px * C2 + 32] = rb;
    }
}

extern "C" void kernel_launch(void* const* d_in, const int* in_sizes, int n_in,
                              void* d_out, int out_size)
{
    const float2* fm2  = (const float2*)d_in[0];   // (1,64,64,128) fp32
    const int*    rois = (const int*)d_in[1];      // (1,N,4) int32
    float2*       out2 = (float2*)d_out;           // (1,N,7,7,128) fp32

    const int n_rois = in_sizes[1] / 4;

    roi_pool_kernel<<<n_rois, 224>>>(fm2, rois, out2, n_rois);
}